// round 1
// baseline (speedup 1.0000x reference)
#include <cuda_runtime.h>
#include <cstdint>

#define NEG_BIG (-9000000000000000.0f)
#define LEAKY 0.2f

// ---- scratch (no allocations allowed) ----
__device__ float g_Wh[8 * 2048 * 256];   // 16 MB
__device__ float g_s1[8 * 2048];
__device__ float g_s2[8 * 2048];

// ============================================================
// Kernel 1: Wh[m][o] = sum_f h[m][f] * W[o][f]
//   M = 16384, N(out) = 256, K = 256. Both operands K-contiguous.
//   64x64 tile, BK=16, 256 threads, 4x4 per thread.
// ============================================================
__global__ void k_gemm(const float* __restrict__ A, const float* __restrict__ Bm) {
    const int BK = 16;
    const int PAD = 68;                    // 68*4=272B, 16B-aligned rows, mild conflicts
    __shared__ float As[BK][PAD];
    __shared__ float Bs[BK][PAD];

    int tid = threadIdx.x;                 // 256 threads
    int tx = tid & 15, ty = tid >> 4;
    int m0 = blockIdx.x * 64;
    int n0 = blockIdx.y * 64;

    int lr = tid >> 2;                     // 0..63 row in tile
    int lc = (tid & 3) * 4;                // 0,4,8,12 k-offset
    const float* Aptr = A  + (size_t)(m0 + lr) * 256 + lc;
    const float* Bptr = Bm + (size_t)(n0 + lr) * 256 + lc;

    float acc[4][4];
#pragma unroll
    for (int i = 0; i < 4; i++)
#pragma unroll
        for (int j = 0; j < 4; j++) acc[i][j] = 0.0f;

    for (int k0 = 0; k0 < 256; k0 += BK) {
        float4 va = *(const float4*)(Aptr + k0);
        float4 vb = *(const float4*)(Bptr + k0);
        As[lc + 0][lr] = va.x; As[lc + 1][lr] = va.y;
        As[lc + 2][lr] = va.z; As[lc + 3][lr] = va.w;
        Bs[lc + 0][lr] = vb.x; Bs[lc + 1][lr] = vb.y;
        Bs[lc + 2][lr] = vb.z; Bs[lc + 3][lr] = vb.w;
        __syncthreads();

#pragma unroll
        for (int k = 0; k < BK; k++) {
            float4 a4 = *(const float4*)&As[k][ty * 4];
            float4 b4 = *(const float4*)&Bs[k][tx * 4];
            float am[4] = {a4.x, a4.y, a4.z, a4.w};
            float bn[4] = {b4.x, b4.y, b4.z, b4.w};
#pragma unroll
            for (int i = 0; i < 4; i++)
#pragma unroll
                for (int j = 0; j < 4; j++)
                    acc[i][j] = fmaf(am[i], bn[j], acc[i][j]);
        }
        __syncthreads();
    }

#pragma unroll
    for (int i = 0; i < 4; i++) {
        float* crow = g_Wh + (size_t)(m0 + ty * 4 + i) * 256 + n0 + tx * 4;
        *(float4*)crow = make_float4(acc[i][0], acc[i][1], acc[i][2], acc[i][3]);
    }
}

// ============================================================
// Kernel 2: s1[r] = Wh[r,:]·a1 ; s2[r] = Wh[r,:]·a2  (warp per row)
// ============================================================
__global__ void k_s(const float* __restrict__ a) {
    int row  = blockIdx.x * 8 + (threadIdx.x >> 5);
    int lane = threadIdx.x & 31;
    const float* wh = g_Wh + (size_t)row * 256;

    float v1 = 0.0f, v2 = 0.0f;
#pragma unroll
    for (int k = lane; k < 256; k += 32) {
        float x = wh[k];
        v1 = fmaf(x, a[k],       v1);
        v2 = fmaf(x, a[256 + k], v2);
    }
#pragma unroll
    for (int off = 16; off; off >>= 1) {
        v1 += __shfl_down_sync(0xffffffffu, v1, off);
        v2 += __shfl_down_sync(0xffffffffu, v2, off);
    }
    if (lane == 0) { g_s1[row] = v1; g_s2[row] = v2; }
}

// ============================================================
// Kernel 3: fused masked softmax + AV + ELU.  Warp per row i.
//   Pass 1: online (max, sum) over masked leaky scores.
//   Pass 2: shfl-broadcast weights, accumulate 256-f output,
//           skipping zero-weight (masked) rows warp-uniformly.
// ============================================================
__global__ void k_attn(const int* __restrict__ adj, float* __restrict__ out) {
    __shared__ float s2s[2048];

    int b    = blockIdx.y;
    int warp = threadIdx.x >> 5;
    int lane = threadIdx.x & 31;
    int i    = blockIdx.x * 8 + warp;

    // stage s2 for this batch
    const float* s2g = g_s2 + (size_t)b * 2048;
#pragma unroll
    for (int k = threadIdx.x; k < 2048; k += 256) s2s[k] = s2g[k];
    __syncthreads();

    const int* adjrow = adj + ((size_t)b * 2048 + i) * 2048;
    float s1i = g_s1[(size_t)b * 2048 + i];

    // ---- pass 1: online max/sum ----
    float m = -__int_as_float(0x7f800000) * 1.0f;  // -inf
    m = -INFINITY;
    float sum = 0.0f;
    for (int j = lane; j < 2048; j += 32) {
        int   aij = adjrow[j];
        float e   = s1i + s2s[j];
        e = (e > 0.0f) ? e : LEAKY * e;
        e = aij ? e : NEG_BIG;
        float nm = fmaxf(m, e);
        sum = sum * __expf(m - nm) + __expf(e - nm);
        m = nm;
    }
#pragma unroll
    for (int off = 16; off; off >>= 1) {
        float om = __shfl_down_sync(0xffffffffu, m,   off);
        float os = __shfl_down_sync(0xffffffffu, sum, off);
        float nm = fmaxf(m, om);
        sum = sum * __expf(m - nm) + os * __expf(om - nm);
        m = nm;
    }
    m   = __shfl_sync(0xffffffffu, m,   0);
    sum = __shfl_sync(0xffffffffu, sum, 0);
    float rinv = 1.0f / sum;

    // ---- pass 2: weighted accumulation of Wh rows ----
    const float4* whb = (const float4*)(g_Wh + (size_t)b * 2048 * 256);
    float4 acc0 = make_float4(0.f, 0.f, 0.f, 0.f);
    float4 acc1 = make_float4(0.f, 0.f, 0.f, 0.f);

    for (int jc = 0; jc < 2048; jc += 32) {
        int   aij = adjrow[jc + lane];
        float e   = s1i + s2s[jc + lane];
        e = (e > 0.0f) ? e : LEAKY * e;
        float w = aij ? __expf(e - m) : 0.0f;

#pragma unroll
        for (int jj = 0; jj < 32; jj++) {
            float wj = __shfl_sync(0xffffffffu, w, jj);
            if (wj != 0.0f) {                       // warp-uniform skip (~50% of rows)
                const float4* whrow = whb + (size_t)(jc + jj) * 64;
                float4 v0 = whrow[lane];
                float4 v1 = whrow[lane + 32];
                acc0.x = fmaf(wj, v0.x, acc0.x);
                acc0.y = fmaf(wj, v0.y, acc0.y);
                acc0.z = fmaf(wj, v0.z, acc0.z);
                acc0.w = fmaf(wj, v0.w, acc0.w);
                acc1.x = fmaf(wj, v1.x, acc1.x);
                acc1.y = fmaf(wj, v1.y, acc1.y);
                acc1.z = fmaf(wj, v1.z, acc1.z);
                acc1.w = fmaf(wj, v1.w, acc1.w);
            }
        }
    }

    // normalize + ELU + store
    float4* orow = (float4*)(out + ((size_t)b * 2048 + i) * 256);
    float r[8] = {acc0.x, acc0.y, acc0.z, acc0.w, acc1.x, acc1.y, acc1.z, acc1.w};
#pragma unroll
    for (int t = 0; t < 8; t++) {
        float x = r[t] * rinv;
        r[t] = (x > 0.0f) ? x : (expm1f(x));
    }
    orow[lane]      = make_float4(r[0], r[1], r[2], r[3]);
    orow[lane + 32] = make_float4(r[4], r[5], r[6], r[7]);
}

// ============================================================
extern "C" void kernel_launch(void* const* d_in, const int* in_sizes, int n_in,
                              void* d_out, int out_size) {
    const float* h   = (const float*)d_in[0];
    const int*   adj = (const int*)  d_in[1];
    const float* W   = (const float*)d_in[2];
    const float* a   = (const float*)d_in[3];
    float* out = (float*)d_out;

    dim3 g1(16384 / 64, 256 / 64);          // 256 x 4
    k_gemm<<<g1, 256>>>(h, W);

    k_s<<<16384 / 8, 256>>>(a);

    dim3 g2(2048 / 8, 8);                   // 256 x 8
    k_attn<<<g2, 256>>>(adj, out);
}

// round 2
// speedup vs baseline: 2.8609x; 2.8609x over previous
#include <cuda_runtime.h>
#include <cstdint>

#define NEG_BIG (-9000000000000000.0f)
#define LEAKY 0.2f

// ---- scratch (static device globals; no runtime allocation) ----
__device__ float g_Wh[8ul * 2048 * 256];          // 16 MB
__device__ float g_P [8ul * 2048 * 2048];         // 134 MB (normalized attention)
__device__ float g_s1[8 * 2048];
__device__ float g_s2[8 * 2048];

// fp32 -> tf32 (round to nearest) kept in a 32-bit float container
__device__ __forceinline__ float f2tf32(float x) {
    uint32_t u;
    asm("cvt.rna.tf32.f32 %0, %1;" : "=r"(u) : "f"(x));
    return __uint_as_float(u);
}

// ============================================================
// Kernel 1: Wh[m][o] = sum_f h[m][f] * W[o][f]   (fp32 tiled)
// ============================================================
__global__ void k_gemm(const float* __restrict__ A, const float* __restrict__ Bm) {
    const int BK = 16;
    const int PAD = 68;
    __shared__ float As[BK][PAD];
    __shared__ float Bs[BK][PAD];

    int tid = threadIdx.x;
    int tx = tid & 15, ty = tid >> 4;
    int m0 = blockIdx.x * 64;
    int n0 = blockIdx.y * 64;

    int lr = tid >> 2;
    int lc = (tid & 3) * 4;
    const float* Aptr = A  + (size_t)(m0 + lr) * 256 + lc;
    const float* Bptr = Bm + (size_t)(n0 + lr) * 256 + lc;

    float acc[4][4];
#pragma unroll
    for (int i = 0; i < 4; i++)
#pragma unroll
        for (int j = 0; j < 4; j++) acc[i][j] = 0.0f;

    for (int k0 = 0; k0 < 256; k0 += BK) {
        float4 va = *(const float4*)(Aptr + k0);
        float4 vb = *(const float4*)(Bptr + k0);
        As[lc + 0][lr] = va.x; As[lc + 1][lr] = va.y;
        As[lc + 2][lr] = va.z; As[lc + 3][lr] = va.w;
        Bs[lc + 0][lr] = vb.x; Bs[lc + 1][lr] = vb.y;
        Bs[lc + 2][lr] = vb.z; Bs[lc + 3][lr] = vb.w;
        __syncthreads();

#pragma unroll
        for (int k = 0; k < BK; k++) {
            float4 a4 = *(const float4*)&As[k][ty * 4];
            float4 b4 = *(const float4*)&Bs[k][tx * 4];
            float am[4] = {a4.x, a4.y, a4.z, a4.w};
            float bn[4] = {b4.x, b4.y, b4.z, b4.w};
#pragma unroll
            for (int i = 0; i < 4; i++)
#pragma unroll
                for (int j = 0; j < 4; j++)
                    acc[i][j] = fmaf(am[i], bn[j], acc[i][j]);
        }
        __syncthreads();
    }

#pragma unroll
    for (int i = 0; i < 4; i++) {
        float* crow = g_Wh + (size_t)(m0 + ty * 4 + i) * 256 + n0 + tx * 4;
        *(float4*)crow = make_float4(acc[i][0], acc[i][1], acc[i][2], acc[i][3]);
    }
}

// ============================================================
// Kernel 2: s1[r] = Wh[r,:]·a1 ; s2[r] = Wh[r,:]·a2
// ============================================================
__global__ void k_s(const float* __restrict__ a) {
    int row  = blockIdx.x * 8 + (threadIdx.x >> 5);
    int lane = threadIdx.x & 31;
    const float* wh = g_Wh + (size_t)row * 256;

    float v1 = 0.0f, v2 = 0.0f;
#pragma unroll
    for (int k = lane; k < 256; k += 32) {
        float x = wh[k];
        v1 = fmaf(x, a[k],       v1);
        v2 = fmaf(x, a[256 + k], v2);
    }
#pragma unroll
    for (int off = 16; off; off >>= 1) {
        v1 += __shfl_down_sync(0xffffffffu, v1, off);
        v2 += __shfl_down_sync(0xffffffffu, v2, off);
    }
    if (lane == 0) { g_s1[row] = v1; g_s2[row] = v2; }
}

// ============================================================
// Kernel 3: masked-leaky softmax, writes NORMALIZED P row.
//   One block (256 thr) per (i, b) row. Single adj read.
// ============================================================
__global__ __launch_bounds__(256) void k_softmax(const int* __restrict__ adj) {
    __shared__ float es[2048];
    __shared__ float redm[8];
    __shared__ float redsum[8];

    int i = blockIdx.x;
    int b = blockIdx.y;
    int tid  = threadIdx.x;
    int wid  = tid >> 5;
    int lane = tid & 31;

    const int*   arow = adj + ((size_t)b * 2048 + i) * 2048;
    const float* s2   = g_s2 + (size_t)b * 2048;
    float s1i = g_s1[(size_t)b * 2048 + i];

    float lm = -INFINITY;
#pragma unroll
    for (int j = tid; j < 2048; j += 256) {
        float e = s1i + s2[j];
        e = (e > 0.0f) ? e : LEAKY * e;
        e = arow[j] ? e : NEG_BIG;
        es[j] = e;
        lm = fmaxf(lm, e);
    }
#pragma unroll
    for (int off = 16; off; off >>= 1)
        lm = fmaxf(lm, __shfl_xor_sync(0xffffffffu, lm, off));
    if (lane == 0) redm[wid] = lm;
    __syncthreads();

    float m = redm[0];
#pragma unroll
    for (int w = 1; w < 8; w++) m = fmaxf(m, redm[w]);

    float ls = 0.0f;
#pragma unroll
    for (int j = tid; j < 2048; j += 256) {
        float p = __expf(es[j] - m);
        es[j] = p;
        ls += p;
    }
#pragma unroll
    for (int off = 16; off; off >>= 1)
        ls += __shfl_xor_sync(0xffffffffu, ls, off);
    if (lane == 0) redsum[wid] = ls;
    __syncthreads();

    float sum = 0.0f;
#pragma unroll
    for (int w = 0; w < 8; w++) sum += redsum[w];
    float rinv = 1.0f / sum;

    float* prow = g_P + ((size_t)b * 2048 + i) * 2048;
#pragma unroll
    for (int j = tid; j < 2048; j += 256)
        prow[j] = es[j] * rinv;
}

// ============================================================
// Kernel 4: out = elu(P @ Wh) via tf32 mma.sync (m16n8k8)
//   BM=64, BN=256 (full), BK=16. 8 warps, warp tile 32x64.
// ============================================================
__device__ __forceinline__ void mma_tf32(float* d, const float* a, const float* b) {
    asm volatile(
        "mma.sync.aligned.m16n8k8.row.col.f32.tf32.tf32.f32 "
        "{%0,%1,%2,%3}, {%4,%5,%6,%7}, {%8,%9}, {%0,%1,%2,%3};"
        : "+f"(d[0]), "+f"(d[1]), "+f"(d[2]), "+f"(d[3])
        : "r"(__float_as_uint(a[0])), "r"(__float_as_uint(a[1])),
          "r"(__float_as_uint(a[2])), "r"(__float_as_uint(a[3])),
          "r"(__float_as_uint(b[0])), "r"(__float_as_uint(b[1])));
}

__global__ __launch_bounds__(256) void k_av(float* __restrict__ out) {
    __shared__ float As[64][20];    // [m][k], stride 20 (frag loads conflict-free)
    __shared__ float Bs[16][264];   // [k][n], stride 264 == 8 mod 32 (conflict-free)

    int b  = blockIdx.y;
    int m0 = blockIdx.x * 64;
    int tid  = threadIdx.x;
    int wid  = tid >> 5, lane = tid & 31;
    int g = lane >> 2, tig = lane & 3;
    int warpM = wid >> 2;       // 0..1 -> 32 rows
    int warpN = wid & 3;        // 0..3 -> 64 cols

    const float* Pb  = g_P  + ((size_t)b * 2048 + m0) * 2048;
    const float* Whb = g_Wh + (size_t)b * 2048 * 256;

    float acc[2][8][4];
#pragma unroll
    for (int mt = 0; mt < 2; mt++)
#pragma unroll
        for (int nt = 0; nt < 8; nt++)
#pragma unroll
            for (int c = 0; c < 4; c++) acc[mt][nt][c] = 0.0f;

    int ar = tid >> 2;          // 0..63
    int ac = (tid & 3) * 4;     // 0,4,8,12

    for (int k0 = 0; k0 < 2048; k0 += 16) {
        // A tile: P[m0+ar][k0+ac..+3]
        float4 va = *(const float4*)(Pb + (size_t)ar * 2048 + k0 + ac);
        As[ar][ac + 0] = f2tf32(va.x);
        As[ar][ac + 1] = f2tf32(va.y);
        As[ar][ac + 2] = f2tf32(va.z);
        As[ar][ac + 3] = f2tf32(va.w);

        // B tile: Wh[k0+row][col..col+3], 4 float4 per thread
#pragma unroll
        for (int p = 0; p < 4; p++) {
            int idx = tid + p * 256;       // float4 units, 1024 total
            int row = idx >> 6;            // 64 float4 per row
            int col = (idx & 63) * 4;
            float4 vb = *(const float4*)(Whb + (size_t)(k0 + row) * 256 + col);
            Bs[row][col + 0] = f2tf32(vb.x);
            Bs[row][col + 1] = f2tf32(vb.y);
            Bs[row][col + 2] = f2tf32(vb.z);
            Bs[row][col + 3] = f2tf32(vb.w);
        }
        __syncthreads();

#pragma unroll
        for (int kc = 0; kc < 2; kc++) {
            int kb = kc * 8;
            float afr[2][4];
#pragma unroll
            for (int mt = 0; mt < 2; mt++) {
                int mrow = warpM * 32 + mt * 16;
                afr[mt][0] = As[mrow + g    ][kb + tig    ];
                afr[mt][1] = As[mrow + g + 8][kb + tig    ];
                afr[mt][2] = As[mrow + g    ][kb + tig + 4];
                afr[mt][3] = As[mrow + g + 8][kb + tig + 4];
            }
            float bfr[8][2];
#pragma unroll
            for (int nt = 0; nt < 8; nt++) {
                int ncol = warpN * 64 + nt * 8 + g;
                bfr[nt][0] = Bs[kb + tig    ][ncol];
                bfr[nt][1] = Bs[kb + tig + 4][ncol];
            }
#pragma unroll
            for (int mt = 0; mt < 2; mt++)
#pragma unroll
                for (int nt = 0; nt < 8; nt++)
                    mma_tf32(acc[mt][nt], afr[mt], bfr[nt]);
        }
        __syncthreads();
    }

    // epilogue: ELU + store (float2 per c-pair)
#pragma unroll
    for (int mt = 0; mt < 2; mt++) {
#pragma unroll
        for (int nt = 0; nt < 8; nt++) {
            int m = m0 + warpM * 32 + mt * 16 + g;
            int n = warpN * 64 + nt * 8 + 2 * tig;
            float c0 = acc[mt][nt][0], c1 = acc[mt][nt][1];
            float c2 = acc[mt][nt][2], c3 = acc[mt][nt][3];
            c0 = (c0 > 0.0f) ? c0 : expm1f(c0);
            c1 = (c1 > 0.0f) ? c1 : expm1f(c1);
            c2 = (c2 > 0.0f) ? c2 : expm1f(c2);
            c3 = (c3 > 0.0f) ? c3 : expm1f(c3);
            float* o0 = out + ((size_t)b * 2048 + m) * 256 + n;
            float* o1 = out + ((size_t)b * 2048 + m + 8) * 256 + n;
            *(float2*)o0 = make_float2(c0, c1);
            *(float2*)o1 = make_float2(c2, c3);
        }
    }
}

// ============================================================
extern "C" void kernel_launch(void* const* d_in, const int* in_sizes, int n_in,
                              void* d_out, int out_size) {
    const float* h   = (const float*)d_in[0];
    const int*   adj = (const int*)  d_in[1];
    const float* W   = (const float*)d_in[2];
    const float* a   = (const float*)d_in[3];
    float* out = (float*)d_out;

    dim3 g1(16384 / 64, 256 / 64);
    k_gemm<<<g1, 256>>>(h, W);

    k_s<<<16384 / 8, 256>>>(a);

    dim3 g3(2048, 8);
    k_softmax<<<g3, 256>>>(adj);

    dim3 g4(2048 / 64, 8);
    k_av<<<g4, 256>>>(out);
}